// round 1
// baseline (speedup 1.0000x reference)
#include <cuda_runtime.h>
#include <cstdint>

#define BB 64
#define TT 2000
#define LLEN 400
#define MMEL 80
#define EPSF 1e-8f

// Global accumulators (no allocation allowed): 0 = sum|mel_out-tgt|,
// 1 = sum|postnet-tgt|, 2 = gate BCE sum, 3 = KL sum, 4 = entropy sum.
__device__ double g_acc[5];

__global__ void k_zero() {
    if (threadIdx.x < 5) g_acc[threadIdx.x] = 0.0;
}

__device__ __forceinline__ float warp_sum(float v) {
#pragma unroll
    for (int o = 16; o > 0; o >>= 1) v += __shfl_xor_sync(0xffffffffu, v, o);
    return v;
}

// ---------------------------------------------------------------------------
// Kernel 1: mel L1 losses (float4, validity-skipped) + gate BCE (fused)
// ---------------------------------------------------------------------------
__global__ void k_melgate(const float* __restrict__ post,
                          const float* __restrict__ mo,
                          const float* __restrict__ gate_out,
                          const float* __restrict__ tgt,
                          const float* __restrict__ gate_tgt,
                          const int*   __restrict__ mel_len) {
    __shared__ int s_len[BB];
    for (int i = threadIdx.x; i < BB; i += blockDim.x) s_len[i] = mel_len[i];
    __syncthreads();

    const int tid      = blockIdx.x * blockDim.x + threadIdx.x;
    const int nthreads = gridDim.x * blockDim.x;

    float s1 = 0.f, s2 = 0.f, sg = 0.f;

    const int N4 = BB * TT * MMEL / 4;   // 2,560,000 float4 per tensor
    const float4* p4 = (const float4*)post;
    const float4* o4 = (const float4*)mo;
    const float4* t4 = (const float4*)tgt;

    for (int i = tid; i < N4; i += nthreads) {
        int bt = i / 20;                  // 80/4 = 20 float4 per (b,t) row
        int b  = bt / TT;
        int t  = bt - b * TT;
        if (t < s_len[b]) {
            float4 a = o4[i], c = t4[i], p = p4[i];
            s1 += fabsf(a.x - c.x) + fabsf(a.y - c.y) +
                  fabsf(a.z - c.z) + fabsf(a.w - c.w);
            s2 += fabsf(p.x - c.x) + fabsf(p.y - c.y) +
                  fabsf(p.z - c.z) + fabsf(p.w - c.w);
        }
    }

    for (int i = tid; i < BB * TT; i += nthreads) {
        float x = gate_out[i];
        float z = gate_tgt[i];
        sg += fmaxf(x, 0.f) - x * z + log1pf(__expf(-fabsf(x)));
    }

    // block reduce
    __shared__ float red[3][8];
    float w1 = warp_sum(s1), w2 = warp_sum(s2), w3 = warp_sum(sg);
    int wid = threadIdx.x >> 5, lane = threadIdx.x & 31;
    int nwarps = blockDim.x >> 5;
    if (lane == 0) { red[0][wid] = w1; red[1][wid] = w2; red[2][wid] = w3; }
    __syncthreads();
    if (threadIdx.x == 0) {
        float a = 0.f, b = 0.f, c = 0.f;
        for (int i = 0; i < nwarps; i++) { a += red[0][i]; b += red[1][i]; c += red[2][i]; }
        atomicAdd(&g_acc[0], (double)a);
        atomicAdd(&g_acc[1], (double)b);
        atomicAdd(&g_acc[2], (double)c);
    }
}

// ---------------------------------------------------------------------------
// Kernel 2: attention KL + entropy, one warp per (b,t) row.
// KL row closed-form: with g_l = exp(-0.5 z^2), S = sum g, S' = S + EPS,
//   KL = E1/S' - (S/S') * log(S'),  E1 = sum g * (log g - log a)
// (log g = -0.5 z^2 analytically — no extra MUFU).
// ---------------------------------------------------------------------------
__global__ void k_attn(const float* __restrict__ attn,
                       const int*   __restrict__ text_len) {
    const int gwarp = (blockIdx.x * blockDim.x + threadIdx.x) >> 5;
    const int lane  = threadIdx.x & 31;

    float kl_w = 0.f, ent_w = 0.f;

    if (gwarp < BB * TT) {
        int r  = gwarp;
        int b  = r / TT;
        int t  = r - b * TT;
        int Lb = text_len[b];

        float sigma   = fminf(fmaxf((float)Lb * 0.05f, 3.0f), 10.0f);
        int   ep_i    = t * Lb / TT;
        if (ep_i > Lb - 1) ep_i = Lb - 1;
        float exp_pos = (float)ep_i;
        float inv_sig = 1.0f / sigma;

        const float* row = attn + (size_t)r * LLEN;

        float S = 0.f, E1 = 0.f, ent = 0.f;
#pragma unroll 4
        for (int l = lane; l < LLEN; l += 32) {
            float a  = __ldg(row + l);
            float as = fmaxf(a, EPSF);
            float la = __logf(as);
            ent -= as * la;
            if (l < Lb) {
                float z  = ((float)l - exp_pos) * inv_sig;
                float lg = -0.5f * z * z;
                float g  = __expf(lg);
                S  += g;
                E1 += g * (lg - la);
            }
        }
        S   = warp_sum(S);
        E1  = warp_sum(E1);
        ent = warp_sum(ent);
        if (lane == 0) {
            float Sp = S + EPSF;
            kl_w  = E1 / Sp - (S / Sp) * __logf(Sp);
            ent_w = ent;
        }
    }

    // block reduce (lane 0 of each warp holds the row's values)
    __shared__ float red[2][8];
    int wid = threadIdx.x >> 5;
    int nwarps = blockDim.x >> 5;
    if (lane == 0) { red[0][wid] = kl_w; red[1][wid] = ent_w; }
    __syncthreads();
    if (threadIdx.x == 0) {
        float a = 0.f, b = 0.f;
        for (int i = 0; i < nwarps; i++) { a += red[0][i]; b += red[1][i]; }
        atomicAdd(&g_acc[3], (double)a);
        atomicAdd(&g_acc[4], (double)b);
    }
}

// ---------------------------------------------------------------------------
// Kernel 3: finalize -> 4 scalars
// ---------------------------------------------------------------------------
__global__ void k_final(const int* __restrict__ mel_len, float* __restrict__ out) {
    if (threadIdx.x == 0) {
        long long s = 0;
        for (int b = 0; b < BB; b++) s += mel_len[b];
        double n_valid  = (double)s * (double)MMEL;
        double mel_loss = (g_acc[0] + g_acc[1]) / n_valid;
        double gate     = g_acc[2] / (double)(BB * TT);
        double kl       = g_acc[3] / (double)BB / (double)TT;
        if (kl > 150.0) kl = 150.0;
        double ent   = g_acc[4] / (double)(BB * TT);
        double ratio = ent / 3.5; if (ratio < 0.0) ratio = 0.0;
        double w     = (ent <= 3.5) ? fmax(0.2, 1.0 * ratio) : 1.0;
        double total = mel_loss + gate + w * kl;
        out[0] = (float)total;
        out[1] = (float)mel_loss;
        out[2] = (float)gate;
        out[3] = (float)kl;
    }
}

extern "C" void kernel_launch(void* const* d_in, const int* in_sizes, int n_in,
                              void* d_out, int out_size) {
    const float* post     = (const float*)d_in[0];  // mel_out_postnet
    const float* mo       = (const float*)d_in[1];  // mel_out
    const float* gate_out = (const float*)d_in[2];  // gate_out
    const float* attn     = (const float*)d_in[3];  // alignments
    const float* tgt      = (const float*)d_in[4];  // mel_target
    const float* gate_tgt = (const float*)d_in[5];  // gate_target
    const int*   mel_len  = (const int*)  d_in[6];  // mel_lengths
    const int*   text_len = (const int*)  d_in[7];  // text_lengths
    float* out = (float*)d_out;

    k_zero<<<1, 32>>>();
    k_melgate<<<1184, 256>>>(post, mo, gate_out, tgt, gate_tgt, mel_len);
    k_attn<<<(BB * TT + 7) / 8, 256>>>(attn, text_len);  // 8 warps/block, 1 warp/row
    k_final<<<1, 32>>>(mel_len, out);
}

// round 3
// speedup vs baseline: 1.3615x; 1.3615x over previous
#include <cuda_runtime.h>
#include <cstdint>

#define BB 64
#define TT 2000
#define LLEN 400
#define MMEL 80
#define EPSF 1e-8f

#define NBLOCKS 1184      // 148 SMs x 8 blocks
#define NTHREADS 256

// Global accumulators: 0 = sum|mel_out-tgt|, 1 = sum|postnet-tgt|,
// 2 = gate BCE sum, 3 = KL sum, 4 = entropy sum.
// Zero at static init; last block resets them after finalize -> deterministic
// across graph replays.
__device__ double g_acc[5];
__device__ unsigned int g_done;

__device__ __forceinline__ float warp_sum(float v) {
#pragma unroll
    for (int o = 16; o > 0; o >>= 1) v += __shfl_xor_sync(0xffffffffu, v, o);
    return v;
}

__device__ __forceinline__ int warp_sum_i(int v) {
#pragma unroll
    for (int o = 16; o > 0; o >>= 1) v += __shfl_xor_sync(0xffffffffu, v, o);
    return v;
}

__global__ void __launch_bounds__(NTHREADS, 8)
k_fused(const float* __restrict__ post,
        const float* __restrict__ mo,
        const float* __restrict__ gate_out,
        const float* __restrict__ attn,
        const float* __restrict__ tgt,
        const float* __restrict__ gate_tgt,
        const int*   __restrict__ mel_len,
        const int*   __restrict__ text_len,
        float* __restrict__ out) {
    __shared__ int s_len[BB];
    for (int i = threadIdx.x; i < BB; i += NTHREADS) s_len[i] = mel_len[i];
    __syncthreads();

    const int tid      = blockIdx.x * NTHREADS + threadIdx.x;
    const int nthreads = NBLOCKS * NTHREADS;
    const int lane     = threadIdx.x & 31;
    const int wid      = threadIdx.x >> 5;

    // ---------------- Part A: mel L1 (float4, validity-skipped) + gate BCE --
    float s1 = 0.f, s2 = 0.f, sg = 0.f;
    {
        const int N4 = BB * TT * MMEL / 4;           // 2,560,000
        const float4* p4 = (const float4*)post;
        const float4* o4 = (const float4*)mo;
        const float4* t4 = (const float4*)tgt;

        for (int i = tid; i < N4; i += nthreads) {
            int bt = i / 20;                          // 20 float4 per (b,t)
            int b  = bt / TT;
            int t  = bt - b * TT;
            if (t < s_len[b]) {
                float4 a = o4[i], c = t4[i], p = p4[i];
                s1 += fabsf(a.x - c.x) + fabsf(a.y - c.y) +
                      fabsf(a.z - c.z) + fabsf(a.w - c.w);
                s2 += fabsf(p.x - c.x) + fabsf(p.y - c.y) +
                      fabsf(p.z - c.z) + fabsf(p.w - c.w);
            }
        }
        for (int i = tid; i < BB * TT; i += nthreads) {
            float x = gate_out[i];
            float z = gate_tgt[i];
            sg += fmaxf(x, 0.f) - x * z + log1pf(__expf(-fabsf(x)));
        }
    }

    // ---------------- Part B: attention KL + entropy, one warp per row ------
    // Closed form per row: g = exp(-0.5 z^2), S = sum g, S' = S + EPS,
    //   KL = E1/S' - (S/S') * log S',  E1 = sum g*(-0.5 z^2 - log a).
    float kl_acc = 0.f, ent_acc = 0.f;
    {
        const int gwarp  = (blockIdx.x * (NTHREADS / 32)) + wid;
        const int nwarps = NBLOCKS * (NTHREADS / 32);

        for (int r = gwarp; r < BB * TT; r += nwarps) {
            int b  = r / TT;
            int t  = r - b * TT;
            int Lb = text_len[b];

            float sigma   = fminf(fmaxf((float)Lb * 0.05f, 3.0f), 10.0f);
            int   ep_i    = t * Lb / TT;
            if (ep_i > Lb - 1) ep_i = Lb - 1;
            float exp_pos = (float)ep_i;
            float inv_sig = 1.0f / sigma;

            const float4* row4 = (const float4*)(attn + (size_t)r * LLEN);

            float S = 0.f, E1 = 0.f, ent = 0.f;
#pragma unroll 1
            for (int q = lane; q < LLEN / 4; q += 32) {   // 100 float4
                float4 av = __ldg(row4 + q);
                int l0 = q * 4;
#pragma unroll
                for (int j = 0; j < 4; j++) {
                    float a  = (j == 0) ? av.x : (j == 1) ? av.y : (j == 2) ? av.z : av.w;
                    int   l  = l0 + j;
                    float as = fmaxf(a, EPSF);
                    float la = __logf(as);
                    ent -= as * la;
                    if (l < Lb) {
                        float z  = ((float)l - exp_pos) * inv_sig;
                        float lg = -0.5f * z * z;
                        float g  = __expf(lg);
                        S  += g;
                        E1 += g * (lg - la);
                    }
                }
            }
            S   = warp_sum(S);
            E1  = warp_sum(E1);
            ent = warp_sum(ent);
            if (lane == 0) {
                float Sp = S + EPSF;
                kl_acc  += E1 / Sp - (S / Sp) * __logf(Sp);
                ent_acc += ent;
            }
        }
    }

    // ---------------- Block reduce + global accumulate ----------------------
    __shared__ float red[5][NTHREADS / 32];
    s1 = warp_sum(s1); s2 = warp_sum(s2); sg = warp_sum(sg);
    // kl_acc/ent_acc live only in lane 0 of each warp
    if (lane == 0) {
        red[0][wid] = s1; red[1][wid] = s2; red[2][wid] = sg;
        red[3][wid] = kl_acc; red[4][wid] = ent_acc;
    }
    __syncthreads();
    if (threadIdx.x == 0) {
        float p0 = 0.f, p1 = 0.f, p2 = 0.f, p3 = 0.f, p4 = 0.f;
        for (int i = 0; i < NTHREADS / 32; i++) {
            p0 += red[0][i]; p1 += red[1][i]; p2 += red[2][i];
            p3 += red[3][i]; p4 += red[4][i];
        }
        atomicAdd(&g_acc[0], (double)p0);
        atomicAdd(&g_acc[1], (double)p1);
        atomicAdd(&g_acc[2], (double)p2);
        atomicAdd(&g_acc[3], (double)p3);
        atomicAdd(&g_acc[4], (double)p4);
    }

    // ---------------- Last block: finalize + reset --------------------------
    __shared__ bool is_last;
    __threadfence();
    if (threadIdx.x == 0) {
        unsigned v = atomicAdd(&g_done, 1u);
        is_last = (v == (unsigned)(NBLOCKS - 1));
    }
    __syncthreads();

    if (is_last && threadIdx.x < 32) {
        int s = mel_len[threadIdx.x] + mel_len[threadIdx.x + 32];
        s = warp_sum_i(s);
        if (threadIdx.x == 0) {
            double n_valid  = (double)s * (double)MMEL;
            double mel_loss = (g_acc[0] + g_acc[1]) / n_valid;
            double gate     = g_acc[2] / (double)(BB * TT);
            double kl       = g_acc[3] / (double)BB / (double)TT;
            if (kl > 150.0) kl = 150.0;
            double ent   = g_acc[4] / (double)(BB * TT);
            double ratio = ent / 3.5; if (ratio < 0.0) ratio = 0.0;
            double w     = (ent <= 3.5) ? fmax(0.2, ratio) : 1.0;
            out[0] = (float)(mel_loss + gate + w * kl);
            out[1] = (float)mel_loss;
            out[2] = (float)gate;
            out[3] = (float)kl;
            // reset for next (deterministic) replay
            g_acc[0] = 0.0; g_acc[1] = 0.0; g_acc[2] = 0.0;
            g_acc[3] = 0.0; g_acc[4] = 0.0;
            __threadfence();
            g_done = 0u;
        }
    }
}

extern "C" void kernel_launch(void* const* d_in, const int* in_sizes, int n_in,
                              void* d_out, int out_size) {
    const float* post     = (const float*)d_in[0];  // mel_out_postnet
    const float* mo       = (const float*)d_in[1];  // mel_out
    const float* gate_out = (const float*)d_in[2];  // gate_out
    const float* attn     = (const float*)d_in[3];  // alignments
    const float* tgt      = (const float*)d_in[4];  // mel_target
    const float* gate_tgt = (const float*)d_in[5];  // gate_target
    const int*   mel_len  = (const int*)  d_in[6];  // mel_lengths
    const int*   text_len = (const int*)  d_in[7];  // text_lengths
    float* out = (float*)d_out;

    k_fused<<<NBLOCKS, NTHREADS>>>(post, mo, gate_out, attn, tgt, gate_tgt,
                                   mel_len, text_len, out);
}

// round 7
// speedup vs baseline: 1.5848x; 1.1640x over previous
#include <cuda_runtime.h>
#include <cstdint>

#define BB 64
#define TT 2000
#define LLEN 400
#define MMEL 80
#define EPSF 1e-8f

#define NBLOCKS 1180            // 1180*256 = 302080 = 20 * 15104  (mod-20 trick)
#define NTHREADS 256
#define TOTTHREADS (NBLOCKS * NTHREADS)
#define DBT 15104               // stride in (b,t)-rows = TOTTHREADS/20
#define DB  7                   // DBT / TT
#define DT  1104                // DBT % TT

__device__ double g_acc[5];     // 0:|mo-tgt| 1:|post-tgt| 2:gate 3:kl 4:ent
__device__ unsigned int g_done;

__device__ __forceinline__ float warp_sum(float v) {
#pragma unroll
    for (int o = 16; o > 0; o >>= 1) v += __shfl_xor_sync(0xffffffffu, v, o);
    return v;
}
__device__ __forceinline__ int warp_sum_i(int v) {
#pragma unroll
    for (int o = 16; o > 0; o >>= 1) v += __shfl_xor_sync(0xffffffffu, v, o);
    return v;
}

__global__ void __launch_bounds__(NTHREADS, 8)
k_fused(const float* __restrict__ post,
        const float* __restrict__ mo,
        const float* __restrict__ gate_out,
        const float* __restrict__ attn,
        const float* __restrict__ tgt,
        const float* __restrict__ gate_tgt,
        const int*   __restrict__ mel_len,
        const int*   __restrict__ text_len,
        float* __restrict__ out) {
    __shared__ int s_mlen[BB];
    __shared__ int s_tlen[BB];
    for (int i = threadIdx.x; i < BB; i += NTHREADS) {
        s_mlen[i] = mel_len[i];
        s_tlen[i] = text_len[i];
    }
    __syncthreads();

    const int tid  = blockIdx.x * NTHREADS + threadIdx.x;
    const int lane = threadIdx.x & 31;
    const int wid  = threadIdx.x >> 5;

    // ---------------- Part A: mel L1 (float4, validity-skipped) -------------
    float s1 = 0.f, s2 = 0.f, sg = 0.f;
    {
        const float4* p4 = (const float4*)post;
        const float4* o4 = (const float4*)mo;
        const float4* t4 = (const float4*)tgt;

        int bt   = tid / 20;           // once
        int part = tid - bt * 20;
        int b    = bt / TT;
        int t    = bt - b * TT;
        size_t idx = (size_t)bt * 20 + part;

        while (bt < BB * TT) {
            if (t < s_mlen[b]) {
                float4 a = o4[idx], c = t4[idx], p = p4[idx];
                s1 += fabsf(a.x - c.x) + fabsf(a.y - c.y) +
                      fabsf(a.z - c.z) + fabsf(a.w - c.w);
                s2 += fabsf(p.x - c.x) + fabsf(p.y - c.y) +
                      fabsf(p.z - c.z) + fabsf(p.w - c.w);
            }
            bt  += DBT;
            idx += TOTTHREADS;
            t   += DT; b += DB;
            if (t >= TT) { t -= TT; b += 1; }
        }
        for (int i = tid; i < BB * TT; i += TOTTHREADS) {
            float x = gate_out[i];
            float z = gate_tgt[i];
            sg += fmaxf(x, 0.f) - x * z + log1pf(__expf(-fabsf(x)));
        }
    }

    // ---------------- Part B: attn KL + entropy, one warp per row -----------
    // KL closed form: g = exp(-0.5 z^2) (6-sigma window), S' = S + EPS,
    //   KL_row = E1/S' - (S/S') log S',  E1 = sum g*(-0.5 z^2 - log a).
    float kl_acc = 0.f, ent_acc = 0.f;
    {
        const int gwarp  = blockIdx.x * (NTHREADS / 32) + wid;
        const int nwarps = NBLOCKS * (NTHREADS / 32);

        for (int r = gwarp; r < BB * TT; r += nwarps) {
            int b  = r / TT;
            int t  = r - b * TT;
            int Lb = s_tlen[b];

            float sigma   = fminf(fmaxf((float)Lb * 0.05f, 3.0f), 10.0f);
            float inv_sig = 1.0f / sigma;
            int   e       = t * Lb / TT;
            if (e > Lb - 1) e = Lb - 1;
            int   w       = (int)(6.0f * sigma) + 1;
            int   lo      = e - w; if (lo < 0) lo = 0;
            int   hi      = e + w; if (hi > Lb) hi = Lb;
            float ef      = (float)e;

            const float4* row4 = (const float4*)(attn + (size_t)r * LLEN);

            float S = 0.f, E1 = 0.f;
#pragma unroll 1
            for (int q = lane; q < LLEN / 4; q += 32) {   // 100 float4
                float4 av = __ldg(row4 + q);
                int l0 = q * 4;
                float la0 = __logf(fmaxf(av.x, EPSF));
                float la1 = __logf(fmaxf(av.y, EPSF));
                float la2 = __logf(fmaxf(av.z, EPSF));
                float la3 = __logf(fmaxf(av.w, EPSF));
                ent_acc -= fmaxf(av.x, EPSF) * la0 + fmaxf(av.y, EPSF) * la1 +
                           fmaxf(av.z, EPSF) * la2 + fmaxf(av.w, EPSF) * la3;
                if (l0 + 3 >= lo && l0 < hi) {
                    float la[4] = {la0, la1, la2, la3};
#pragma unroll
                    for (int j = 0; j < 4; j++) {
                        int l = l0 + j;
                        if (l >= lo && l < hi) {
                            float z  = ((float)l - ef) * inv_sig;
                            float lg = -0.5f * z * z;
                            float g  = __expf(lg);
                            S  += g;
                            E1 += g * (lg - la[j]);
                        }
                    }
                }
            }
            S  = warp_sum(S);
            E1 = warp_sum(E1);
            if (lane == 0) {
                float Sp = S + EPSF;
                kl_acc += E1 / Sp - (S / Sp) * __logf(Sp);
            }
        }
    }

    // ---------------- Block reduce + global accumulate ----------------------
    __shared__ float red[5][NTHREADS / 32];
    s1 = warp_sum(s1); s2 = warp_sum(s2); sg = warp_sum(sg);
    kl_acc = warp_sum(kl_acc);           // only lane0 nonzero per warp
    ent_acc = warp_sum(ent_acc);
    if (lane == 0) {
        red[0][wid] = s1; red[1][wid] = s2; red[2][wid] = sg;
        red[3][wid] = kl_acc; red[4][wid] = ent_acc;
    }
    __syncthreads();
    if (threadIdx.x == 0) {
        float p0 = 0.f, p1 = 0.f, p2 = 0.f, p3 = 0.f, p4 = 0.f;
        for (int i = 0; i < NTHREADS / 32; i++) {
            p0 += red[0][i]; p1 += red[1][i]; p2 += red[2][i];
            p3 += red[3][i]; p4 += red[4][i];
        }
        atomicAdd(&g_acc[0], (double)p0);
        atomicAdd(&g_acc[1], (double)p1);
        atomicAdd(&g_acc[2], (double)p2);
        atomicAdd(&g_acc[3], (double)p3);
        atomicAdd(&g_acc[4], (double)p4);
    }

    // ---------------- Last block: finalize + reset --------------------------
    __shared__ bool is_last;
    __threadfence();
    if (threadIdx.x == 0) {
        unsigned v = atomicAdd(&g_done, 1u);
        is_last = (v == (unsigned)(NBLOCKS - 1));
    }
    __syncthreads();

    if (is_last && threadIdx.x < 32) {
        int s = s_mlen[threadIdx.x] + s_mlen[threadIdx.x + 32];
        s = warp_sum_i(s);
        if (threadIdx.x == 0) {
            double n_valid  = (double)s * (double)MMEL;
            double mel_loss = (g_acc[0] + g_acc[1]) / n_valid;
            double gate     = g_acc[2] / (double)(BB * TT);
            double kl       = g_acc[3] / (double)BB / (double)TT;
            if (kl > 150.0) kl = 150.0;
            double ent   = g_acc[4] / (double)(BB * TT);
            double ratio = ent / 3.5; if (ratio < 0.0) ratio = 0.0;
            double wgt   = (ent <= 3.5) ? fmax(0.2, ratio) : 1.0;
            out[0] = (float)(mel_loss + gate + wgt * kl);
            out[1] = (float)mel_loss;
            out[2] = (float)gate;
            out[3] = (float)kl;
            g_acc[0] = 0.0; g_acc[1] = 0.0; g_acc[2] = 0.0;
            g_acc[3] = 0.0; g_acc[4] = 0.0;
            __threadfence();
            g_done = 0u;
        }
    }
}

extern "C" void kernel_launch(void* const* d_in, const int* in_sizes, int n_in,
                              void* d_out, int out_size) {
    const float* post     = (const float*)d_in[0];
    const float* mo       = (const float*)d_in[1];
    const float* gate_out = (const float*)d_in[2];
    const float* attn     = (const float*)d_in[3];
    const float* tgt      = (const float*)d_in[4];
    const float* gate_tgt = (const float*)d_in[5];
    const int*   mel_len  = (const int*)  d_in[6];
    const int*   text_len = (const int*)  d_in[7];
    float* out = (float*)d_out;

    k_fused<<<NBLOCKS, NTHREADS>>>(post, mo, gate_out, attn, tgt, gate_tgt,
                                   mel_len, text_len, out);
}

// round 9
// speedup vs baseline: 1.6656x; 1.0510x over previous
#include <cuda_runtime.h>
#include <cstdint>

#define BB 64
#define TT 2000
#define LLEN 400
#define MMEL 80
#define EPSF 1e-8f
#define LN2 0.6931471805599453

#define NBLOCKS 1180            // 1180*256 = 302080 = 20*15104 (mod-20 trick)
#define NTHREADS 256
#define TOTTHREADS (NBLOCKS * NTHREADS)
#define DBT 15104               // row stride for mel = TOTTHREADS/20
#define DB  7
#define DT  1104

#define NWARPS (NBLOCKS * (NTHREADS / 32))   // 9440
#define ADB 4                   // NWARPS / TT
#define ADT 1440                // NWARPS % TT

__device__ double g_acc[5];     // 0:|mo-tgt| 1:|post-tgt| 2:gate 3:kl2 4:ent2
__device__ unsigned int g_done;

__device__ __forceinline__ float warp_sum(float v) {
#pragma unroll
    for (int o = 16; o > 0; o >>= 1) v += __shfl_xor_sync(0xffffffffu, v, o);
    return v;
}
__device__ __forceinline__ int warp_sum_i(int v) {
#pragma unroll
    for (int o = 16; o > 0; o >>= 1) v += __shfl_xor_sync(0xffffffffu, v, o);
    return v;
}

// entropy (log2 space) for one float4; a==1.0 contributes exactly 0.
__device__ __forceinline__ void ent4(float4 v, float& ent2) {
    float a0 = fmaxf(v.x, EPSF), a1 = fmaxf(v.y, EPSF);
    float a2 = fmaxf(v.z, EPSF), a3 = fmaxf(v.w, EPSF);
    ent2 -= a0 * __log2f(a0);
    ent2 -= a1 * __log2f(a1);
    ent2 -= a2 * __log2f(a2);
    ent2 -= a3 * __log2f(a3);
}

// ---------------- mel L1 + gate BCE ----------------------------------------
__device__ __forceinline__ void do_melgate(
    const float* __restrict__ post, const float* __restrict__ mo,
    const float* __restrict__ tgt,  const float* __restrict__ gate_out,
    const float* __restrict__ gate_tgt, const int* __restrict__ s_mlen,
    int tid, float& s1, float& s2, float& sg) {
    const float4* p4 = (const float4*)post;
    const float4* o4 = (const float4*)mo;
    const float4* t4 = (const float4*)tgt;

    int bt   = tid / 20;
    int part = tid - bt * 20;
    int b    = bt / TT;
    int t    = bt - b * TT;
    size_t idx = (size_t)bt * 20 + part;

    while (bt < BB * TT) {
        if (t < s_mlen[b]) {
            float4 a = o4[idx], c = t4[idx], p = p4[idx];
            s1 += fabsf(a.x - c.x) + fabsf(a.y - c.y) +
                  fabsf(a.z - c.z) + fabsf(a.w - c.w);
            s2 += fabsf(p.x - c.x) + fabsf(p.y - c.y) +
                  fabsf(p.z - c.z) + fabsf(p.w - c.w);
        }
        bt  += DBT;
        idx += TOTTHREADS;
        t   += DT; b += DB;
        if (t >= TT) { t -= TT; b += 1; }
    }
    for (int i = tid; i < BB * TT; i += TOTTHREADS) {
        float x = gate_out[i];
        float z = gate_tgt[i];
        sg += fmaxf(x, 0.f) - x * z + log1pf(__expf(-fabsf(x)));
    }
}

// ---------------- attn KL + entropy ----------------------------------------
__device__ __forceinline__ void do_attn(
    const float* __restrict__ attn, const int* __restrict__ s_tlen,
    const float* __restrict__ s_c, const int* __restrict__ s_w,
    int gwarp, int lane, float& kl2_acc, float& ent2_acc) {

    int r = gwarp;
    int b = r / TT;
    int t = r - b * TT;

    const float4 one4 = make_float4(1.f, 1.f, 1.f, 1.f);

    while (r < BB * TT) {
        const int   Lb = s_tlen[b];
        const float c  = s_c[b];
        const int   w  = s_w[b];

        int e = t * Lb / TT;
        if (e > Lb - 1) e = Lb - 1;
        int lo = e - w; if (lo < 0) lo = 0;
        int hi = e + w; if (hi > Lb) hi = Lb;
        float ef = (float)e;

        const float4* row4 = (const float4*)(attn + (size_t)r * LLEN);

        // --- entropy: branch-free, batched loads (MLP=4) ---
        float4 v0 = __ldg(row4 + lane);
        float4 v1 = __ldg(row4 + lane + 32);
        float4 v2 = __ldg(row4 + lane + 64);
        float4 v3 = (lane < 4) ? __ldg(row4 + 96 + lane) : one4;
        ent4(v0, ent2_acc); ent4(v1, ent2_acc);
        ent4(v2, ent2_acc); ent4(v3, ent2_acc);

        // --- Gaussian window (<=32 float4s in practice; L1 re-hit) ---
        float S = 0.f, E12 = 0.f;
        int lo4 = lo >> 2;
        int hi4 = (hi + 3) >> 2;
        for (int q = lo4 + lane; q < hi4; q += 32) {
            float4 av = __ldg(row4 + q);
            int l0 = q * 4;
#pragma unroll
            for (int j = 0; j < 4; j++) {
                float a = (j == 0) ? av.x : (j == 1) ? av.y : (j == 2) ? av.z : av.w;
                int l = l0 + j;
                if (l >= lo && l < hi) {
                    float d   = (float)l - ef;
                    float y   = -c * d * d;          // lg2(g)
                    float g   = exp2f(y);
                    float la2 = __log2f(fmaxf(a, EPSF));
                    S   += g;
                    E12 += g * (y - la2);
                }
            }
        }
        S   = warp_sum(S);
        E12 = warp_sum(E12);
        if (lane == 0) {
            float Sp = S + EPSF;
            kl2_acc += E12 / Sp - (S / Sp) * __log2f(Sp);
        }

        r += NWARPS;
        t += ADT; b += ADB;
        if (t >= TT) { t -= TT; b += 1; }
    }
}

__global__ void __launch_bounds__(NTHREADS)
k_fused(const float* __restrict__ post,
        const float* __restrict__ mo,
        const float* __restrict__ gate_out,
        const float* __restrict__ attn,
        const float* __restrict__ tgt,
        const float* __restrict__ gate_tgt,
        const int*   __restrict__ mel_len,
        const int*   __restrict__ text_len,
        float* __restrict__ out) {
    __shared__ int   s_mlen[BB];
    __shared__ int   s_tlen[BB];
    __shared__ float s_c[BB];       // 0.5*log2e / sigma^2
    __shared__ int   s_w[BB];       // 6*sigma + 1
    if (threadIdx.x < BB) {
        int Lb = text_len[threadIdx.x];
        s_mlen[threadIdx.x] = mel_len[threadIdx.x];
        s_tlen[threadIdx.x] = Lb;
        float sigma = fminf(fmaxf((float)Lb * 0.05f, 3.0f), 10.0f);
        s_c[threadIdx.x] = 0.7213475204444817f / (sigma * sigma);
        s_w[threadIdx.x] = (int)(6.0f * sigma) + 1;
    }
    __syncthreads();

    const int tid   = blockIdx.x * NTHREADS + threadIdx.x;
    const int lane  = threadIdx.x & 31;
    const int wid   = threadIdx.x >> 5;
    const int gwarp = blockIdx.x * (NTHREADS / 32) + wid;

    float s1 = 0.f, s2 = 0.f, sg = 0.f, kl2 = 0.f, ent2 = 0.f;

    // Phase interleave: odd blocks attn-first -> DRAM-heavy and issue-heavy
    // work co-resident on every SM throughout the kernel.
    if (blockIdx.x & 1) {
        do_attn(attn, s_tlen, s_c, s_w, gwarp, lane, kl2, ent2);
        do_melgate(post, mo, tgt, gate_out, gate_tgt, s_mlen, tid, s1, s2, sg);
    } else {
        do_melgate(post, mo, tgt, gate_out, gate_tgt, s_mlen, tid, s1, s2, sg);
        do_attn(attn, s_tlen, s_c, s_w, gwarp, lane, kl2, ent2);
    }

    // ---------------- block reduce + global accumulate ----------------------
    __shared__ float red[5][NTHREADS / 32];
    s1 = warp_sum(s1); s2 = warp_sum(s2); sg = warp_sum(sg);
    kl2 = warp_sum(kl2);                 // nonzero only in lane 0 already
    ent2 = warp_sum(ent2);
    if (lane == 0) {
        red[0][wid] = s1; red[1][wid] = s2; red[2][wid] = sg;
        red[3][wid] = kl2; red[4][wid] = ent2;
    }
    __syncthreads();
    if (threadIdx.x == 0) {
        float p0 = 0.f, p1 = 0.f, p2 = 0.f, p3 = 0.f, p4 = 0.f;
        for (int i = 0; i < NTHREADS / 32; i++) {
            p0 += red[0][i]; p1 += red[1][i]; p2 += red[2][i];
            p3 += red[3][i]; p4 += red[4][i];
        }
        atomicAdd(&g_acc[0], (double)p0);
        atomicAdd(&g_acc[1], (double)p1);
        atomicAdd(&g_acc[2], (double)p2);
        atomicAdd(&g_acc[3], (double)p3);
        atomicAdd(&g_acc[4], (double)p4);
    }

    // ---------------- last block: finalize + reset --------------------------
    __shared__ bool is_last;
    __threadfence();
    if (threadIdx.x == 0) {
        unsigned v = atomicAdd(&g_done, 1u);
        is_last = (v == (unsigned)(NBLOCKS - 1));
    }
    __syncthreads();

    if (is_last && threadIdx.x < 32) {
        int s = s_mlen[threadIdx.x] + s_mlen[threadIdx.x + 32];
        s = warp_sum_i(s);
        if (threadIdx.x == 0) {
            double n_valid  = (double)s * (double)MMEL;
            double mel_loss = (g_acc[0] + g_acc[1]) / n_valid;
            double gate     = g_acc[2] / (double)(BB * TT);
            double kl       = LN2 * g_acc[3] / (double)BB / (double)TT;
            if (kl > 150.0) kl = 150.0;
            double ent   = LN2 * g_acc[4] / (double)(BB * TT);
            double ratio = ent / 3.5; if (ratio < 0.0) ratio = 0.0;
            double wgt   = (ent <= 3.5) ? fmax(0.2, ratio) : 1.0;
            out[0] = (float)(mel_loss + gate + wgt * kl);
            out[1] = (float)mel_loss;
            out[2] = (float)gate;
            out[3] = (float)kl;
            g_acc[0] = 0.0; g_acc[1] = 0.0; g_acc[2] = 0.0;
            g_acc[3] = 0.0; g_acc[4] = 0.0;
            __threadfence();
            g_done = 0u;
        }
    }
}

extern "C" void kernel_launch(void* const* d_in, const int* in_sizes, int n_in,
                              void* d_out, int out_size) {
    const float* post     = (const float*)d_in[0];
    const float* mo       = (const float*)d_in[1];
    const float* gate_out = (const float*)d_in[2];
    const float* attn     = (const float*)d_in[3];
    const float* tgt      = (const float*)d_in[4];
    const float* gate_tgt = (const float*)d_in[5];
    const int*   mel_len  = (const int*)  d_in[6];
    const int*   text_len = (const int*)  d_in[7];
    float* out = (float*)d_out;

    k_fused<<<NBLOCKS, NTHREADS>>>(post, mo, gate_out, attn, tgt, gate_tgt,
                                   mel_len, text_len, out);
}